// round 12
// baseline (speedup 1.0000x reference)
#include <cuda_runtime.h>
#include <math.h>
#include <string.h>

// ---------------------------------------------------------------------------
// Problem constants
// ---------------------------------------------------------------------------
#define NM_MAX 50000
#define ND_MAX 20000
#define EMAX   700000
#define FEAT   128
#define SCAN_CHUNK 2048   // elements per CSR-scan block (256 thr x 8)

// Scratch (device globals: allocation-free rule)
__device__ float g_agg1 [(size_t)NM_MAX * FEAT];
__device__ float g_movie[(size_t)NM_MAX * FEAT];
__device__ float g_agg2 [(size_t)ND_MAX * FEAT];
__device__ float g_user1[(size_t)ND_MAX * FEAT];
__device__ float g_agg3 [(size_t)ND_MAX * FEAT];
__device__ float g_user2[(size_t)ND_MAX * FEAT];

// CSR-build scratch
__device__ int   g_cnt_m[NM_MAX + 1];
__device__ int   g_off_m[NM_MAX + 1];
__device__ int   g_cur_m[NM_MAX];
__device__ int   g_perm_m[EMAX];
__device__ int   g_cnt_b[ND_MAX + 1];
__device__ int   g_off_b[ND_MAX + 1];
__device__ int   g_cur_b[ND_MAX];
__device__ int   g_perm_b[EMAX];
__device__ float g_ews[EMAX];     // sigmoid(edge_weight)
__device__ int   g_part_m[32];    // per-block partial sums (n <= 65536)
__device__ int   g_part_b[32];

// ---------------------------------------------------------------------------
// Helpers: packed f32x2 FMA (full-rate fp32 on sm_103a)
// ---------------------------------------------------------------------------
__device__ __forceinline__ void ffma2(unsigned long long& acc,
                                      unsigned long long a,
                                      unsigned long long b) {
    asm("fma.rn.f32x2 %0, %1, %2, %3;" : "=l"(acc) : "l"(a), "l"(b), "l"(acc));
}
__device__ __forceinline__ unsigned long long pack2(float lo, float hi) {
    unsigned long long r;
    asm("mov.b64 %0, {%1, %2};" : "=l"(r) : "f"(lo), "f"(hi));
    return r;
}

// ---------------------------------------------------------------------------
// CSR build
// ---------------------------------------------------------------------------
__global__ __launch_bounds__(256)
void hist_kernel(const int* __restrict__ dst_m, const int* __restrict__ dst_b,
                 const float* __restrict__ ew, int E) {
    int e = blockIdx.x * 256 + threadIdx.x;
    if (e >= E) return;
    atomicAdd(&g_cnt_m[__ldg(dst_m + e)], 1);
    atomicAdd(&g_cnt_b[__ldg(dst_b + e)], 1);
    g_ews[e] = 1.f / (1.f + __expf(-__ldg(ew + e)));
}

// Phase 1: per-block partial sums (both graphs packed in one grid)
__device__ __forceinline__ void reduce_body(const int* __restrict__ cnt,
                                            int* __restrict__ part, int n, int blk) {
    __shared__ int sw[8];
    int t = threadIdx.x;
    int base = blk * SCAN_CHUNK + t * 8;
    int s = 0;
#pragma unroll
    for (int j = 0; j < 8; ++j) {
        int i = base + j;
        if (i < n) s += __ldg(cnt + i);
    }
    for (int o = 16; o > 0; o >>= 1) s += __shfl_down_sync(0xffffffffu, s, o);
    if ((t & 31) == 0) sw[t >> 5] = s;
    __syncthreads();
    if (t < 8) {
        int v = sw[t];
        for (int o = 4; o > 0; o >>= 1) v += __shfl_down_sync(0xffu, v, o);
        if (t == 0) part[blk] = v;
    }
}
__global__ __launch_bounds__(256)
void csr_reduce(int n_m, int n_d, int nb_m) {
    if ((int)blockIdx.x < nb_m) reduce_body(g_cnt_m, g_part_m, n_m, blockIdx.x);
    else                        reduce_body(g_cnt_b, g_part_b, n_d, blockIdx.x - nb_m);
}

// Phase 2: tiny scan of partials (warp 0 -> m, warp 1 -> b), in-place exclusive
__global__ __launch_bounds__(64)
void csr_scanmid(int nb_m, int nb_b) {
    int w = threadIdx.x >> 5, lane = threadIdx.x & 31;
    int* part = w ? g_part_b : g_part_m;
    int  nb   = w ? nb_b : nb_m;
    int v = (lane < nb) ? part[lane] : 0;
    int x = v;
    for (int o = 1; o < 32; o <<= 1) {
        int y = __shfl_up_sync(0xffffffffu, x, o);
        if (lane >= o) x += y;
    }
    if (lane < nb) part[lane] = x - v;   // exclusive base per block
}

// Phase 3: per-block exclusive scan, write offs[] and cur[]; tail writes offs[n]
__device__ __forceinline__ void offs_body(const int* __restrict__ cnt,
                                          const int* __restrict__ part,
                                          int* __restrict__ offs, int* __restrict__ cur,
                                          int n, int blk) {
    __shared__ int sw[8];
    int t = threadIdx.x, lane = t & 31, wid = t >> 5;
    int base = blk * SCAN_CHUNK + t * 8;
    int c[8]; int s = 0;
#pragma unroll
    for (int j = 0; j < 8; ++j) {
        int i = base + j;
        c[j] = (i < n) ? __ldg(cnt + i) : 0;
        s += c[j];
    }
    int x = s;
    for (int o = 1; o < 32; o <<= 1) {
        int y = __shfl_up_sync(0xffffffffu, x, o);
        if (lane >= o) x += y;
    }
    if (lane == 31) sw[wid] = x;
    __syncthreads();
    if (wid == 0) {
        int v = (lane < 8) ? sw[lane] : 0;
        for (int o = 1; o < 8; o <<= 1) {
            int y = __shfl_up_sync(0xffffffffu, v, o);
            if (lane >= o) v += y;
        }
        if (lane < 8) sw[lane] = v;
    }
    __syncthreads();
    int run = part[blk] + (wid ? sw[wid - 1] : 0) + x - s;  // global exclusive
#pragma unroll
    for (int j = 0; j < 8; ++j) {
        int i = base + j;
        if (i < n) {
            offs[i] = run;
            cur[i]  = run;
            run += c[j];
            if (i == n - 1) offs[n] = run;
        }
    }
}
__global__ __launch_bounds__(256)
void csr_offsets(int n_m, int n_d, int nb_m) {
    if ((int)blockIdx.x < nb_m)
        offs_body(g_cnt_m, g_part_m, g_off_m, g_cur_m, n_m, blockIdx.x);
    else
        offs_body(g_cnt_b, g_part_b, g_off_b, g_cur_b, n_d, blockIdx.x - nb_m);
}

// Phase 4: fill edge-id permutations for both graphs
__global__ __launch_bounds__(256)
void fill_kernel(const int* __restrict__ dst_m, const int* __restrict__ dst_b, int E) {
    int e = blockIdx.x * 256 + threadIdx.x;
    if (e >= E) return;
    int p = atomicAdd(&g_cur_m[__ldg(dst_m + e)], 1);
    g_perm_m[p] = e;
    int q = atomicAdd(&g_cur_b[__ldg(dst_b + e)], 1);
    g_perm_b[q] = e;
}

// ---------------------------------------------------------------------------
// Gather-based aggregation: one warp per dst node, no atomics.
// ---------------------------------------------------------------------------
template <bool WEIGHTED>
__global__ __launch_bounds__(256)
void agg_gather(const float* __restrict__ x,
                const int*   __restrict__ src,
                const int*   __restrict__ perm,
                const int*   __restrict__ offs,
                float*       __restrict__ agg,
                int n_dst) {
    int d = blockIdx.x * 8 + (threadIdx.x >> 5);
    if (d >= n_dst) return;
    const int lane  = threadIdx.x & 31;
    const int start = __ldg(offs + d);
    const int end   = __ldg(offs + d + 1);

    float4 acc = make_float4(0.f, 0.f, 0.f, 0.f);
    for (int base = start; base < end; base += 32) {
        int i = base + lane;
        int e = (i < end) ? __ldg(perm + i) : 0;
        int s = (i < end) ? __ldg(src + e) : 0;
        float w = 1.f;
        if (WEIGHTED) w = (i < end) ? __ldg(g_ews + e) : 0.f;
        int cnt = min(32, end - base);
#pragma unroll 4
        for (int j = 0; j < cnt; ++j) {
            int   sj = __shfl_sync(0xffffffffu, s, j);
            float wj = WEIGHTED ? __shfl_sync(0xffffffffu, w, j) : 1.f;
            float4 v = *reinterpret_cast<const float4*>(x + (size_t)sj * FEAT + lane * 4);
            if (WEIGHTED) {
                acc.x = fmaf(wj, v.x, acc.x);
                acc.y = fmaf(wj, v.y, acc.y);
                acc.z = fmaf(wj, v.z, acc.z);
                acc.w = fmaf(wj, v.w, acc.w);
            } else {
                acc.x += v.x; acc.y += v.y; acc.z += v.z; acc.w += v.w;
            }
        }
    }
    *reinterpret_cast<float4*>(agg + (size_t)d * FEAT + lane * 4) = acc;
}

// ---------------------------------------------------------------------------
// Fused GraphConv GEMM, double-buffered smem pipeline, generalized tiles:
//   out[m,n] = act( A1[m,:]@W1[:,n] + (HAS2 ? A2[m,:]@W2[:,n] : 0) + bias[n] )
// 256 threads; thread tile TM x TN; block tile BM x BN; K = 128 per pass.
// __launch_bounds__(256, 3): 3 CTAs/SM -> single-wave grids, higher occupancy.
// ---------------------------------------------------------------------------
template <int BM, int TM, int BN, int TN, bool HAS2, bool RELU>
__global__ __launch_bounds__(256, 3)
void gemm_fused(const float* __restrict__ A1, const float* __restrict__ W1,
                const float* __restrict__ A2, const float* __restrict__ W2,
                const float* __restrict__ bias,
                float* __restrict__ out, int M) {
    constexpr int BK = 8, K = 128;
    constexpr int TPP = K / BK;                 // tiles per pass = 16
    constexpr int NT  = HAS2 ? 2 * TPP : TPP;   // total k-tiles
    static_assert((BM / TM) * (BN / TN) == 256, "thread layout");
    static_assert(TM % 4 == 0 && TN % 4 == 0, "vector tiles");

    __shared__ float sA[2][BK][BM + 4];
    __shared__ float sB[2][BK][BN + 4];

    const int t = threadIdx.x;
    const int rowBase = blockIdx.x * BM;
    const int tm0 = (t / (BN / TN)) * TM;
    const int tn0 = (t % (BN / TN)) * TN;

    // A-tile load: one float4 per active thread (BM*BK/4 quads)
    const bool aact = t < (BM * BK / 4);
    const int  ar   = t >> 1;          // row within tile (valid when aact)
    const int  akk  = (t & 1) * 4;     // k-offset of the quad
    const int  agr  = rowBase + ar;
    // B-tile load: one float4 per active thread (BK*BN/4 quads)
    const bool bact = t < (BK * BN / 4);
    const int  bkr  = t / (BN / 4);
    const int  bnc  = (t % (BN / 4)) * 4;

    float4 ra, rb;
    auto loadRegs = [&](int tt) {
        const float* A = (HAS2 && tt >= TPP) ? A2 : A1;
        const float* W = (HAS2 && tt >= TPP) ? W2 : W1;
        const int kt = (HAS2 ? (tt % TPP) : tt) * BK;
        if (aact) {
            ra = make_float4(0.f, 0.f, 0.f, 0.f);
            if (agr < M)
                ra = *reinterpret_cast<const float4*>(A + (size_t)agr * K + kt + akk);
        }
        if (bact)
            rb = *reinterpret_cast<const float4*>(W + (size_t)(kt + bkr) * BN + bnc);
    };
    auto storeRegs = [&](int buf) {
        if (aact) {
            sA[buf][akk + 0][ar] = ra.x;
            sA[buf][akk + 1][ar] = ra.y;
            sA[buf][akk + 2][ar] = ra.z;
            sA[buf][akk + 3][ar] = ra.w;
        }
        if (bact)
            *reinterpret_cast<float4*>(&sB[buf][bkr][bnc]) = rb;
    };

    unsigned long long acc[TM][TN / 2] = {};  // 0 == {+0.f,+0.f}

    loadRegs(0);
    storeRegs(0);
    __syncthreads();

#pragma unroll 1
    for (int tt = 0; tt < NT; ++tt) {
        const int cur = tt & 1;
        if (tt + 1 < NT) loadRegs(tt + 1);

        const float (*pA)[BM + 4] = sA[cur];
        const float (*pB)[BN + 4] = sB[cur];
#pragma unroll
        for (int k = 0; k < BK; ++k) {
            float av[TM];
#pragma unroll
            for (int ii = 0; ii < TM / 4; ++ii) {
                float4 a4 = *reinterpret_cast<const float4*>(&pA[k][tm0 + 4 * ii]);
                av[4 * ii + 0] = a4.x; av[4 * ii + 1] = a4.y;
                av[4 * ii + 2] = a4.z; av[4 * ii + 3] = a4.w;
            }
            float4 bt[TN / 4];
#pragma unroll
            for (int jj = 0; jj < TN / 4; ++jj)
                bt[jj] = *reinterpret_cast<const float4*>(&pB[k][tn0 + 4 * jj]);
            unsigned long long bv[TN / 2];
            memcpy(bv, bt, sizeof(bt));
#pragma unroll
            for (int i = 0; i < TM; ++i) {
                unsigned long long ap = pack2(av[i], av[i]);
#pragma unroll
                for (int j = 0; j < TN / 2; ++j) ffma2(acc[i][j], ap, bv[j]);
            }
        }

        if (tt + 1 < NT) {
            storeRegs(cur ^ 1);
            __syncthreads();
        }
    }

    // --- epilogue: bias (+ReLU) + store ---
#pragma unroll
    for (int i = 0; i < TM; ++i) {
        int gr = rowBase + tm0 + i;
        if (gr < M) {
#pragma unroll
            for (int j = 0; j < TN / 2; ++j) {
                float2 v;
                memcpy(&v, &acc[i][j], 8);
                float o0 = v.x + bias[tn0 + 2 * j];
                float o1 = v.y + bias[tn0 + 2 * j + 1];
                if (RELU) { o0 = fmaxf(o0, 0.f); o1 = fmaxf(o1, 0.f); }
                out[(size_t)gr * BN + tn0 + 2 * j]     = o0;
                out[(size_t)gr * BN + tn0 + 2 * j + 1] = o1;
            }
        }
    }
}

// ---------------------------------------------------------------------------
// Launch
// ---------------------------------------------------------------------------
extern "C" void kernel_launch(void* const* d_in, const int* in_sizes, int n_in,
                              void* d_out, int out_size) {
    const float* x_meas  = (const float*)d_in[0];
    const float* x_dem   = (const float*)d_in[1];
    const int*   src_m   = (const int*)  d_in[2];
    const int*   dst_m   = (const int*)  d_in[3];
    const int*   src_b   = (const int*)  d_in[4];
    const int*   dst_b   = (const int*)  d_in[5];
    const float* eweight = (const float*)d_in[6];
    const float* W_rel1  = (const float*)d_in[7];
    const float* b_rel1  = (const float*)d_in[8];
    const float* W_root1 = (const float*)d_in[9];
    const float* W_rel2  = (const float*)d_in[10];
    const float* b_rel2  = (const float*)d_in[11];
    const float* W_root2 = (const float*)d_in[12];
    const float* W_rel3  = (const float*)d_in[13];
    const float* b_rel3  = (const float*)d_in[14];
    const float* W_root3 = (const float*)d_in[15];
    const float* W_lin   = (const float*)d_in[16];
    const float* b_lin   = (const float*)d_in[17];
    float* out = (float*)d_out;

    const int n_m = in_sizes[0] / FEAT;
    const int n_d = in_sizes[1] / FEAT;
    const int E   = in_sizes[2];

    float *agg1, *agg2, *agg3, *movie, *user1, *user2;
    cudaGetSymbolAddress((void**)&agg1,  g_agg1);
    cudaGetSymbolAddress((void**)&agg2,  g_agg2);
    cudaGetSymbolAddress((void**)&agg3,  g_agg3);
    cudaGetSymbolAddress((void**)&movie, g_movie);
    cudaGetSymbolAddress((void**)&user1, g_user1);
    cudaGetSymbolAddress((void**)&user2, g_user2);
    int *cnt_m, *cnt_b, *off_m, *off_b, *cur_m, *cur_b, *perm_m, *perm_b;
    cudaGetSymbolAddress((void**)&cnt_m,  g_cnt_m);
    cudaGetSymbolAddress((void**)&cnt_b,  g_cnt_b);
    cudaGetSymbolAddress((void**)&off_m,  g_off_m);
    cudaGetSymbolAddress((void**)&off_b,  g_off_b);
    cudaGetSymbolAddress((void**)&cur_m,  g_cur_m);
    cudaGetSymbolAddress((void**)&cur_b,  g_cur_b);
    cudaGetSymbolAddress((void**)&perm_m, g_perm_m);
    cudaGetSymbolAddress((void**)&perm_b, g_perm_b);

    const int eb   = (E + 255) / 256;
    const int nb_m = (n_m + SCAN_CHUNK - 1) / SCAN_CHUNK;   // <= 32
    const int nb_b = (n_d + SCAN_CHUNK - 1) / SCAN_CHUNK;   // <= 32

    // --- CSR build (both graphs, parallel 3-phase scan) ---
    cudaMemsetAsync(cnt_m, 0, (size_t)(n_m + 1) * sizeof(int));
    cudaMemsetAsync(cnt_b, 0, (size_t)(n_d + 1) * sizeof(int));
    hist_kernel<<<eb, 256>>>(dst_m, dst_b, eweight, E);
    csr_reduce<<<nb_m + nb_b, 256>>>(n_m, n_d, nb_m);
    csr_scanmid<<<1, 64>>>(nb_m, nb_b);
    csr_offsets<<<nb_m + nb_b, 256>>>(n_m, n_d, nb_m);
    fill_kernel<<<eb, 256>>>(dst_m, dst_b, E);

    // --- Layer 1 aggregations (gather, no atomics) ---
    agg_gather<false><<<(n_m + 7) / 8, 256>>>(x_meas, src_m, perm_m, off_m, agg1, n_m);
    agg_gather<true ><<<(n_d + 7) / 8, 256>>>(x_meas, src_b, perm_b, off_b, agg2, n_d);

    // --- Layer 1/2 GEMMs ---
    // Big GEMM: 128x128 tiles, 3 CTAs/SM -> 391 blocks in a single wave (cap 444)
    gemm_fused<128, 8, 128, 8, true, true><<<(n_m + 127) / 128, 256>>>(
        agg1, W_rel1, x_meas, W_root1, b_rel1, movie, n_m);
    // Small GEMMs: 64x128 tiles -> 313 blocks fill the whole chip (vs 157 before)
    gemm_fused<64, 4, 128, 8, true, true><<<(n_d + 63) / 64, 256>>>(
        agg2, W_rel2, x_dem, W_root2, b_rel2, user1, n_d);

    // --- Layer 3 aggregation (reuses bipartite CSR) + GEMM ---
    agg_gather<true><<<(n_d + 7) / 8, 256>>>(movie, src_b, perm_b, off_b, agg3, n_d);
    gemm_fused<64, 4, 128, 8, true, true><<<(n_d + 63) / 64, 256>>>(
        agg3, W_rel3, user1, W_root3, b_rel3, user2, n_d);

    // --- Output projection ---
    gemm_fused<64, 4, 64, 4, false, false><<<(n_d + 63) / 64, 256>>>(
        user2, W_lin, nullptr, nullptr, b_lin, out, n_d);
}

// round 13
// speedup vs baseline: 1.2383x; 1.2383x over previous
#include <cuda_runtime.h>
#include <math.h>
#include <string.h>

// ---------------------------------------------------------------------------
// Problem constants
// ---------------------------------------------------------------------------
#define NM_MAX 50000
#define ND_MAX 20000
#define EMAX   700000
#define FEAT   128
#define SCAN_CHUNK 2048   // elements per CSR-scan block (256 thr x 8)

// Scratch (device globals: allocation-free rule)
__device__ float g_agg1 [(size_t)NM_MAX * FEAT];
__device__ float g_movie[(size_t)NM_MAX * FEAT];
__device__ float g_agg2 [(size_t)ND_MAX * FEAT];
__device__ float g_user1[(size_t)ND_MAX * FEAT];
__device__ float g_agg3 [(size_t)ND_MAX * FEAT];
__device__ float g_user2[(size_t)ND_MAX * FEAT];

// CSR-build scratch
__device__ int   g_cnt_m[NM_MAX + 1];
__device__ int   g_off_m[NM_MAX + 1];
__device__ int   g_cur_m[NM_MAX];
__device__ int   g_perm_m[EMAX];
__device__ int   g_cnt_b[ND_MAX + 1];
__device__ int   g_off_b[ND_MAX + 1];
__device__ int   g_cur_b[ND_MAX];
__device__ int   g_perm_b[EMAX];
__device__ float g_ews[EMAX];     // sigmoid(edge_weight)
__device__ int   g_part_m[32];    // per-block partial sums (n <= 65536)
__device__ int   g_part_b[32];

// ---------------------------------------------------------------------------
// Helpers: packed f32x2 FMA (full-rate fp32 on sm_103a)
// ---------------------------------------------------------------------------
__device__ __forceinline__ void ffma2(unsigned long long& acc,
                                      unsigned long long a,
                                      unsigned long long b) {
    asm("fma.rn.f32x2 %0, %1, %2, %3;" : "=l"(acc) : "l"(a), "l"(b), "l"(acc));
}
__device__ __forceinline__ unsigned long long pack2(float lo, float hi) {
    unsigned long long r;
    asm("mov.b64 %0, {%1, %2};" : "=l"(r) : "f"(lo), "f"(hi));
    return r;
}

// ---------------------------------------------------------------------------
// CSR build
// ---------------------------------------------------------------------------
__global__ __launch_bounds__(256)
void hist_kernel(const int* __restrict__ dst_m, const int* __restrict__ dst_b,
                 const float* __restrict__ ew, int E) {
    int e = blockIdx.x * 256 + threadIdx.x;
    if (e >= E) return;
    atomicAdd(&g_cnt_m[__ldg(dst_m + e)], 1);
    atomicAdd(&g_cnt_b[__ldg(dst_b + e)], 1);
    g_ews[e] = 1.f / (1.f + __expf(-__ldg(ew + e)));
}

// Phase 1: per-block partial sums (both graphs packed in one grid)
__device__ __forceinline__ void reduce_body(const int* __restrict__ cnt,
                                            int* __restrict__ part, int n, int blk) {
    __shared__ int sw[8];
    int t = threadIdx.x;
    int base = blk * SCAN_CHUNK + t * 8;
    int s = 0;
#pragma unroll
    for (int j = 0; j < 8; ++j) {
        int i = base + j;
        if (i < n) s += __ldg(cnt + i);
    }
    for (int o = 16; o > 0; o >>= 1) s += __shfl_down_sync(0xffffffffu, s, o);
    if ((t & 31) == 0) sw[t >> 5] = s;
    __syncthreads();
    if (t < 8) {
        int v = sw[t];
        for (int o = 4; o > 0; o >>= 1) v += __shfl_down_sync(0xffu, v, o);
        if (t == 0) part[blk] = v;
    }
}
__global__ __launch_bounds__(256)
void csr_reduce(int n_m, int n_d, int nb_m) {
    if ((int)blockIdx.x < nb_m) reduce_body(g_cnt_m, g_part_m, n_m, blockIdx.x);
    else                        reduce_body(g_cnt_b, g_part_b, n_d, blockIdx.x - nb_m);
}

// Phase 2: tiny scan of partials (warp 0 -> m, warp 1 -> b), in-place exclusive
__global__ __launch_bounds__(64)
void csr_scanmid(int nb_m, int nb_b) {
    int w = threadIdx.x >> 5, lane = threadIdx.x & 31;
    int* part = w ? g_part_b : g_part_m;
    int  nb   = w ? nb_b : nb_m;
    int v = (lane < nb) ? part[lane] : 0;
    int x = v;
    for (int o = 1; o < 32; o <<= 1) {
        int y = __shfl_up_sync(0xffffffffu, x, o);
        if (lane >= o) x += y;
    }
    if (lane < nb) part[lane] = x - v;   // exclusive base per block
}

// Phase 3: per-block exclusive scan, write offs[] and cur[]; tail writes offs[n]
__device__ __forceinline__ void offs_body(const int* __restrict__ cnt,
                                          const int* __restrict__ part,
                                          int* __restrict__ offs, int* __restrict__ cur,
                                          int n, int blk) {
    __shared__ int sw[8];
    int t = threadIdx.x, lane = t & 31, wid = t >> 5;
    int base = blk * SCAN_CHUNK + t * 8;
    int c[8]; int s = 0;
#pragma unroll
    for (int j = 0; j < 8; ++j) {
        int i = base + j;
        c[j] = (i < n) ? __ldg(cnt + i) : 0;
        s += c[j];
    }
    int x = s;
    for (int o = 1; o < 32; o <<= 1) {
        int y = __shfl_up_sync(0xffffffffu, x, o);
        if (lane >= o) x += y;
    }
    if (lane == 31) sw[wid] = x;
    __syncthreads();
    if (wid == 0) {
        int v = (lane < 8) ? sw[lane] : 0;
        for (int o = 1; o < 8; o <<= 1) {
            int y = __shfl_up_sync(0xffffffffu, v, o);
            if (lane >= o) v += y;
        }
        if (lane < 8) sw[lane] = v;
    }
    __syncthreads();
    int run = part[blk] + (wid ? sw[wid - 1] : 0) + x - s;  // global exclusive
#pragma unroll
    for (int j = 0; j < 8; ++j) {
        int i = base + j;
        if (i < n) {
            offs[i] = run;
            cur[i]  = run;
            run += c[j];
            if (i == n - 1) offs[n] = run;
        }
    }
}
__global__ __launch_bounds__(256)
void csr_offsets(int n_m, int n_d, int nb_m) {
    if ((int)blockIdx.x < nb_m)
        offs_body(g_cnt_m, g_part_m, g_off_m, g_cur_m, n_m, blockIdx.x);
    else
        offs_body(g_cnt_b, g_part_b, g_off_b, g_cur_b, n_d, blockIdx.x - nb_m);
}

// Phase 4: fill edge-id permutations for both graphs
__global__ __launch_bounds__(256)
void fill_kernel(const int* __restrict__ dst_m, const int* __restrict__ dst_b, int E) {
    int e = blockIdx.x * 256 + threadIdx.x;
    if (e >= E) return;
    int p = atomicAdd(&g_cur_m[__ldg(dst_m + e)], 1);
    g_perm_m[p] = e;
    int q = atomicAdd(&g_cur_b[__ldg(dst_b + e)], 1);
    g_perm_b[q] = e;
}

// ---------------------------------------------------------------------------
// Gather-based aggregation: one warp per dst node, no atomics.
// ---------------------------------------------------------------------------
template <bool WEIGHTED>
__global__ __launch_bounds__(256)
void agg_gather(const float* __restrict__ x,
                const int*   __restrict__ src,
                const int*   __restrict__ perm,
                const int*   __restrict__ offs,
                float*       __restrict__ agg,
                int n_dst) {
    int d = blockIdx.x * 8 + (threadIdx.x >> 5);
    if (d >= n_dst) return;
    const int lane  = threadIdx.x & 31;
    const int start = __ldg(offs + d);
    const int end   = __ldg(offs + d + 1);

    float4 acc = make_float4(0.f, 0.f, 0.f, 0.f);
    for (int base = start; base < end; base += 32) {
        int i = base + lane;
        int e = (i < end) ? __ldg(perm + i) : 0;
        int s = (i < end) ? __ldg(src + e) : 0;
        float w = 1.f;
        if (WEIGHTED) w = (i < end) ? __ldg(g_ews + e) : 0.f;
        int cnt = min(32, end - base);
#pragma unroll 4
        for (int j = 0; j < cnt; ++j) {
            int   sj = __shfl_sync(0xffffffffu, s, j);
            float wj = WEIGHTED ? __shfl_sync(0xffffffffu, w, j) : 1.f;
            float4 v = *reinterpret_cast<const float4*>(x + (size_t)sj * FEAT + lane * 4);
            if (WEIGHTED) {
                acc.x = fmaf(wj, v.x, acc.x);
                acc.y = fmaf(wj, v.y, acc.y);
                acc.z = fmaf(wj, v.z, acc.z);
                acc.w = fmaf(wj, v.w, acc.w);
            } else {
                acc.x += v.x; acc.y += v.y; acc.z += v.z; acc.w += v.w;
            }
        }
    }
    *reinterpret_cast<float4*>(agg + (size_t)d * FEAT + lane * 4) = acc;
}

// ---------------------------------------------------------------------------
// Fused GraphConv GEMM, double-buffered smem pipeline, generalized tiles:
//   out[m,n] = act( A1[m,:]@W1[:,n] + (HAS2 ? A2[m,:]@W2[:,n] : 0) + bias[n] )
// 256 threads; thread tile TM x TN; block tile BM x BN; K = 128 per pass.
// NOTE: no min-CTAs clause — forcing 3 CTAs/SM spilled the TM=8 inner loop
// (R12: 375->475us). Small tiles (BM=64,TM=4) get occupancy structurally.
// ---------------------------------------------------------------------------
template <int BM, int TM, int BN, int TN, bool HAS2, bool RELU>
__global__ __launch_bounds__(256)
void gemm_fused(const float* __restrict__ A1, const float* __restrict__ W1,
                const float* __restrict__ A2, const float* __restrict__ W2,
                const float* __restrict__ bias,
                float* __restrict__ out, int M) {
    constexpr int BK = 8, K = 128;
    constexpr int TPP = K / BK;                 // tiles per pass = 16
    constexpr int NT  = HAS2 ? 2 * TPP : TPP;   // total k-tiles
    static_assert((BM / TM) * (BN / TN) == 256, "thread layout");
    static_assert(TM % 4 == 0 && TN % 4 == 0, "vector tiles");

    __shared__ float sA[2][BK][BM + 4];
    __shared__ float sB[2][BK][BN + 4];

    const int t = threadIdx.x;
    const int rowBase = blockIdx.x * BM;
    const int tm0 = (t / (BN / TN)) * TM;
    const int tn0 = (t % (BN / TN)) * TN;

    // A-tile load: one float4 per active thread (BM*BK/4 quads)
    constexpr int AQ = BM * BK / 4;           // 256 for BM=128, 128 for BM=64
    const bool aact = t < AQ;
    const int  ar   = t / (BK / 4);           // row within tile
    const int  akk  = (t % (BK / 4)) * 4;     // k-offset of the quad
    const int  agr  = rowBase + ar;
    // B-tile load: one float4 per active thread (BK*BN/4 quads)
    const bool bact = t < (BK * BN / 4);
    const int  bkr  = t / (BN / 4);
    const int  bnc  = (t % (BN / 4)) * 4;

    float4 ra, rb;
    auto loadRegs = [&](int tt) {
        const float* A = (HAS2 && tt >= TPP) ? A2 : A1;
        const float* W = (HAS2 && tt >= TPP) ? W2 : W1;
        const int kt = (HAS2 ? (tt % TPP) : tt) * BK;
        if (aact) {
            ra = make_float4(0.f, 0.f, 0.f, 0.f);
            if (agr < M)
                ra = *reinterpret_cast<const float4*>(A + (size_t)agr * K + kt + akk);
        }
        if (bact)
            rb = *reinterpret_cast<const float4*>(W + (size_t)(kt + bkr) * BN + bnc);
    };
    auto storeRegs = [&](int buf) {
        if (aact) {
            sA[buf][akk + 0][ar] = ra.x;
            sA[buf][akk + 1][ar] = ra.y;
            sA[buf][akk + 2][ar] = ra.z;
            sA[buf][akk + 3][ar] = ra.w;
        }
        if (bact)
            *reinterpret_cast<float4*>(&sB[buf][bkr][bnc]) = rb;
    };

    unsigned long long acc[TM][TN / 2] = {};  // 0 == {+0.f,+0.f}

    loadRegs(0);
    storeRegs(0);
    __syncthreads();

#pragma unroll 1
    for (int tt = 0; tt < NT; ++tt) {
        const int cur = tt & 1;
        if (tt + 1 < NT) loadRegs(tt + 1);

        const float (*pA)[BM + 4] = sA[cur];
        const float (*pB)[BN + 4] = sB[cur];
#pragma unroll
        for (int k = 0; k < BK; ++k) {
            float av[TM];
#pragma unroll
            for (int ii = 0; ii < TM / 4; ++ii) {
                float4 a4 = *reinterpret_cast<const float4*>(&pA[k][tm0 + 4 * ii]);
                av[4 * ii + 0] = a4.x; av[4 * ii + 1] = a4.y;
                av[4 * ii + 2] = a4.z; av[4 * ii + 3] = a4.w;
            }
            float4 bt[TN / 4];
#pragma unroll
            for (int jj = 0; jj < TN / 4; ++jj)
                bt[jj] = *reinterpret_cast<const float4*>(&pB[k][tn0 + 4 * jj]);
            unsigned long long bv[TN / 2];
            memcpy(bv, bt, sizeof(bt));
#pragma unroll
            for (int i = 0; i < TM; ++i) {
                unsigned long long ap = pack2(av[i], av[i]);
#pragma unroll
                for (int j = 0; j < TN / 2; ++j) ffma2(acc[i][j], ap, bv[j]);
            }
        }

        if (tt + 1 < NT) {
            storeRegs(cur ^ 1);
            __syncthreads();
        }
    }

    // --- epilogue: bias (+ReLU) + store ---
#pragma unroll
    for (int i = 0; i < TM; ++i) {
        int gr = rowBase + tm0 + i;
        if (gr < M) {
#pragma unroll
            for (int j = 0; j < TN / 2; ++j) {
                float2 v;
                memcpy(&v, &acc[i][j], 8);
                float o0 = v.x + bias[tn0 + 2 * j];
                float o1 = v.y + bias[tn0 + 2 * j + 1];
                if (RELU) { o0 = fmaxf(o0, 0.f); o1 = fmaxf(o1, 0.f); }
                out[(size_t)gr * BN + tn0 + 2 * j]     = o0;
                out[(size_t)gr * BN + tn0 + 2 * j + 1] = o1;
            }
        }
    }
}

// ---------------------------------------------------------------------------
// Launch
// ---------------------------------------------------------------------------
extern "C" void kernel_launch(void* const* d_in, const int* in_sizes, int n_in,
                              void* d_out, int out_size) {
    const float* x_meas  = (const float*)d_in[0];
    const float* x_dem   = (const float*)d_in[1];
    const int*   src_m   = (const int*)  d_in[2];
    const int*   dst_m   = (const int*)  d_in[3];
    const int*   src_b   = (const int*)  d_in[4];
    const int*   dst_b   = (const int*)  d_in[5];
    const float* eweight = (const float*)d_in[6];
    const float* W_rel1  = (const float*)d_in[7];
    const float* b_rel1  = (const float*)d_in[8];
    const float* W_root1 = (const float*)d_in[9];
    const float* W_rel2  = (const float*)d_in[10];
    const float* b_rel2  = (const float*)d_in[11];
    const float* W_root2 = (const float*)d_in[12];
    const float* W_rel3  = (const float*)d_in[13];
    const float* b_rel3  = (const float*)d_in[14];
    const float* W_root3 = (const float*)d_in[15];
    const float* W_lin   = (const float*)d_in[16];
    const float* b_lin   = (const float*)d_in[17];
    float* out = (float*)d_out;

    const int n_m = in_sizes[0] / FEAT;
    const int n_d = in_sizes[1] / FEAT;
    const int E   = in_sizes[2];

    float *agg1, *agg2, *agg3, *movie, *user1, *user2;
    cudaGetSymbolAddress((void**)&agg1,  g_agg1);
    cudaGetSymbolAddress((void**)&agg2,  g_agg2);
    cudaGetSymbolAddress((void**)&agg3,  g_agg3);
    cudaGetSymbolAddress((void**)&movie, g_movie);
    cudaGetSymbolAddress((void**)&user1, g_user1);
    cudaGetSymbolAddress((void**)&user2, g_user2);
    int *cnt_m, *cnt_b, *off_m, *off_b, *cur_m, *cur_b, *perm_m, *perm_b;
    cudaGetSymbolAddress((void**)&cnt_m,  g_cnt_m);
    cudaGetSymbolAddress((void**)&cnt_b,  g_cnt_b);
    cudaGetSymbolAddress((void**)&off_m,  g_off_m);
    cudaGetSymbolAddress((void**)&off_b,  g_off_b);
    cudaGetSymbolAddress((void**)&cur_m,  g_cur_m);
    cudaGetSymbolAddress((void**)&cur_b,  g_cur_b);
    cudaGetSymbolAddress((void**)&perm_m, g_perm_m);
    cudaGetSymbolAddress((void**)&perm_b, g_perm_b);

    const int eb   = (E + 255) / 256;
    const int nb_m = (n_m + SCAN_CHUNK - 1) / SCAN_CHUNK;   // <= 32
    const int nb_b = (n_d + SCAN_CHUNK - 1) / SCAN_CHUNK;   // <= 32

    // --- CSR build (both graphs, parallel 3-phase scan) ---
    cudaMemsetAsync(cnt_m, 0, (size_t)(n_m + 1) * sizeof(int));
    cudaMemsetAsync(cnt_b, 0, (size_t)(n_d + 1) * sizeof(int));
    hist_kernel<<<eb, 256>>>(dst_m, dst_b, eweight, E);
    csr_reduce<<<nb_m + nb_b, 256>>>(n_m, n_d, nb_m);
    csr_scanmid<<<1, 64>>>(nb_m, nb_b);
    csr_offsets<<<nb_m + nb_b, 256>>>(n_m, n_d, nb_m);
    fill_kernel<<<eb, 256>>>(dst_m, dst_b, E);

    // --- Layer 1 aggregations (gather, no atomics) ---
    agg_gather<false><<<(n_m + 7) / 8, 256>>>(x_meas, src_m, perm_m, off_m, agg1, n_m);
    agg_gather<true ><<<(n_d + 7) / 8, 256>>>(x_meas, src_b, perm_b, off_b, agg2, n_d);

    // --- Layer 1/2 GEMMs ---
    // Big GEMM: 128x128 tiles, unconstrained regs (as in the 375us build)
    gemm_fused<128, 8, 128, 8, true, true><<<(n_m + 127) / 128, 256>>>(
        agg1, W_rel1, x_meas, W_root1, b_rel1, movie, n_m);
    // Small GEMMs: 64x128 tiles -> 313 blocks fill the chip; ~60 regs natural
    gemm_fused<64, 4, 128, 8, true, true><<<(n_d + 63) / 64, 256>>>(
        agg2, W_rel2, x_dem, W_root2, b_rel2, user1, n_d);

    // --- Layer 3 aggregation (reuses bipartite CSR) + GEMM ---
    agg_gather<true><<<(n_d + 7) / 8, 256>>>(movie, src_b, perm_b, off_b, agg3, n_d);
    gemm_fused<64, 4, 128, 8, true, true><<<(n_d + 63) / 64, 256>>>(
        agg3, W_rel3, user1, W_root3, b_rel3, user2, n_d);

    // --- Output projection ---
    gemm_fused<64, 4, 64, 4, false, false><<<(n_d + 63) / 64, 256>>>(
        user2, W_lin, nullptr, nullptr, b_lin, out, n_d);
}

// round 14
// speedup vs baseline: 1.6921x; 1.3665x over previous
#include <cuda_runtime.h>
#include <math.h>
#include <string.h>
#include <stdint.h>

// ---------------------------------------------------------------------------
// Problem constants
// ---------------------------------------------------------------------------
#define NM_MAX 50000
#define ND_MAX 20000
#define EMAX   700000
#define FEAT   128
#define SCAN_CHUNK 2048   // elements per CSR-scan block (256 thr x 8)

// Scratch (device globals: allocation-free rule)
__device__ float g_agg1 [(size_t)NM_MAX * FEAT];
__device__ float g_movie[(size_t)NM_MAX * FEAT];
__device__ float g_agg2 [(size_t)ND_MAX * FEAT];
__device__ float g_user1[(size_t)ND_MAX * FEAT];
__device__ float g_agg3 [(size_t)ND_MAX * FEAT];
__device__ float g_user2[(size_t)ND_MAX * FEAT];

// CSR-build scratch
__device__ int   g_cnt_m[NM_MAX + 1];
__device__ int   g_off_m[NM_MAX + 1];
__device__ int   g_cur_m[NM_MAX];
__device__ int   g_perm_m[EMAX];
__device__ int   g_cnt_b[ND_MAX + 1];
__device__ int   g_off_b[ND_MAX + 1];
__device__ int   g_cur_b[ND_MAX];
__device__ int   g_perm_b[EMAX];
__device__ float g_ews[EMAX];     // sigmoid(edge_weight)
__device__ int   g_part_m[32];    // per-block partial sums (n <= 65536)
__device__ int   g_part_b[32];
__device__ int   g_done;          // last-block flag for fused reduce+scan

// ---------------------------------------------------------------------------
// tf32 helpers
// ---------------------------------------------------------------------------
__device__ __forceinline__ uint32_t f2tf32(float x) {
    uint32_t r;
    asm("cvt.rna.tf32.f32 %0, %1;" : "=r"(r) : "f"(x));
    return r;
}
__device__ __forceinline__ void mma8(float* cc, const uint32_t* a, const uint32_t* b) {
    asm volatile(
        "mma.sync.aligned.m16n8k8.row.col.f32.tf32.tf32.f32 "
        "{%0,%1,%2,%3}, {%4,%5,%6,%7}, {%8,%9}, {%0,%1,%2,%3};"
        : "+f"(cc[0]), "+f"(cc[1]), "+f"(cc[2]), "+f"(cc[3])
        : "r"(a[0]), "r"(a[1]), "r"(a[2]), "r"(a[3]), "r"(b[0]), "r"(b[1]));
}

// ---------------------------------------------------------------------------
// CSR build
// ---------------------------------------------------------------------------
__global__ __launch_bounds__(256)
void zero_counts_kernel(int n_m, int n_d) {
    int i = blockIdx.x * 256 + threadIdx.x;
    if (i <= n_m) g_cnt_m[i] = 0;
    if (i <= n_d) g_cnt_b[i] = 0;
    if (i == 0)   g_done = 0;
}

__global__ __launch_bounds__(256)
void hist_kernel(const int* __restrict__ dst_m, const int* __restrict__ dst_b,
                 const float* __restrict__ ew, int E) {
    int e = blockIdx.x * 256 + threadIdx.x;
    if (e >= E) return;
    atomicAdd(&g_cnt_m[__ldg(dst_m + e)], 1);
    atomicAdd(&g_cnt_b[__ldg(dst_b + e)], 1);
    g_ews[e] = 1.f / (1.f + __expf(-__ldg(ew + e)));
}

__device__ __forceinline__ void reduce_body(const int* __restrict__ cnt,
                                            int* __restrict__ part, int n, int blk) {
    __shared__ int sw[8];
    int t = threadIdx.x;
    int base = blk * SCAN_CHUNK + t * 8;
    int s = 0;
#pragma unroll
    for (int j = 0; j < 8; ++j) {
        int i = base + j;
        if (i < n) s += __ldg(cnt + i);
    }
    for (int o = 16; o > 0; o >>= 1) s += __shfl_down_sync(0xffffffffu, s, o);
    if ((t & 31) == 0) sw[t >> 5] = s;
    __syncthreads();
    if (t < 8) {
        int v = sw[t];
        for (int o = 4; o > 0; o >>= 1) v += __shfl_down_sync(0xffu, v, o);
        if (t == 0) part[blk] = v;
    }
}

// Fused phase 1+2: per-block partial sums, then LAST block scans the partials.
__global__ __launch_bounds__(256)
void csr_reduce_scan(int n_m, int n_d, int nb_m, int nb_b) {
    if ((int)blockIdx.x < nb_m) reduce_body(g_cnt_m, g_part_m, n_m, blockIdx.x);
    else                        reduce_body(g_cnt_b, g_part_b, n_d, blockIdx.x - nb_m);
    __syncthreads();
    __threadfence();
    __shared__ int isLast;
    if (threadIdx.x == 0) {
        int d = atomicAdd(&g_done, 1);
        isLast = (d == (int)gridDim.x - 1);
    }
    __syncthreads();
    if (isLast) {
        if (threadIdx.x == 0) g_done = 0;
        __threadfence();
        if (threadIdx.x < 64) {
            int w = threadIdx.x >> 5, lane = threadIdx.x & 31;
            int* part = w ? g_part_b : g_part_m;
            int  nb   = w ? nb_b : nb_m;
            int v = (lane < nb) ? part[lane] : 0;
            int x = v;
            for (int o = 1; o < 32; o <<= 1) {
                int y = __shfl_up_sync(0xffffffffu, x, o);
                if (lane >= o) x += y;
            }
            if (lane < nb) part[lane] = x - v;   // exclusive base per block
        }
    }
}

// Phase 3: per-block exclusive scan, write offs[] and cur[]
__device__ __forceinline__ void offs_body(const int* __restrict__ cnt,
                                          const int* __restrict__ part,
                                          int* __restrict__ offs, int* __restrict__ cur,
                                          int n, int blk) {
    __shared__ int sw[8];
    int t = threadIdx.x, lane = t & 31, wid = t >> 5;
    int base = blk * SCAN_CHUNK + t * 8;
    int c[8]; int s = 0;
#pragma unroll
    for (int j = 0; j < 8; ++j) {
        int i = base + j;
        c[j] = (i < n) ? __ldg(cnt + i) : 0;
        s += c[j];
    }
    int x = s;
    for (int o = 1; o < 32; o <<= 1) {
        int y = __shfl_up_sync(0xffffffffu, x, o);
        if (lane >= o) x += y;
    }
    if (lane == 31) sw[wid] = x;
    __syncthreads();
    if (wid == 0) {
        int v = (lane < 8) ? sw[lane] : 0;
        for (int o = 1; o < 8; o <<= 1) {
            int y = __shfl_up_sync(0xffffffffu, v, o);
            if (lane >= o) v += y;
        }
        if (lane < 8) sw[lane] = v;
    }
    __syncthreads();
    int run = part[blk] + (wid ? sw[wid - 1] : 0) + x - s;
#pragma unroll
    for (int j = 0; j < 8; ++j) {
        int i = base + j;
        if (i < n) {
            offs[i] = run;
            cur[i]  = run;
            run += c[j];
            if (i == n - 1) offs[n] = run;
        }
    }
}
__global__ __launch_bounds__(256)
void csr_offsets(int n_m, int n_d, int nb_m) {
    if ((int)blockIdx.x < nb_m)
        offs_body(g_cnt_m, g_part_m, g_off_m, g_cur_m, n_m, blockIdx.x);
    else
        offs_body(g_cnt_b, g_part_b, g_off_b, g_cur_b, n_d, blockIdx.x - nb_m);
}

__global__ __launch_bounds__(256)
void fill_kernel(const int* __restrict__ dst_m, const int* __restrict__ dst_b, int E) {
    int e = blockIdx.x * 256 + threadIdx.x;
    if (e >= E) return;
    int p = atomicAdd(&g_cur_m[__ldg(dst_m + e)], 1);
    g_perm_m[p] = e;
    int q = atomicAdd(&g_cur_b[__ldg(dst_b + e)], 1);
    g_perm_b[q] = e;
}

// ---------------------------------------------------------------------------
// Gather-based aggregation: one warp per dst node, no atomics.
// ---------------------------------------------------------------------------
template <bool WEIGHTED>
__global__ __launch_bounds__(256)
void agg_gather(const float* __restrict__ x,
                const int*   __restrict__ src,
                const int*   __restrict__ perm,
                const int*   __restrict__ offs,
                float*       __restrict__ agg,
                int n_dst) {
    int d = blockIdx.x * 8 + (threadIdx.x >> 5);
    if (d >= n_dst) return;
    const int lane  = threadIdx.x & 31;
    const int start = __ldg(offs + d);
    const int end   = __ldg(offs + d + 1);

    float4 acc = make_float4(0.f, 0.f, 0.f, 0.f);
    for (int base = start; base < end; base += 32) {
        int i = base + lane;
        int e = (i < end) ? __ldg(perm + i) : 0;
        int s = (i < end) ? __ldg(src + e) : 0;
        float w = 1.f;
        if (WEIGHTED) w = (i < end) ? __ldg(g_ews + e) : 0.f;
        int cnt = min(32, end - base);
#pragma unroll 4
        for (int j = 0; j < cnt; ++j) {
            int   sj = __shfl_sync(0xffffffffu, s, j);
            float wj = WEIGHTED ? __shfl_sync(0xffffffffu, w, j) : 1.f;
            float4 v = *reinterpret_cast<const float4*>(x + (size_t)sj * FEAT + lane * 4);
            if (WEIGHTED) {
                acc.x = fmaf(wj, v.x, acc.x);
                acc.y = fmaf(wj, v.y, acc.y);
                acc.z = fmaf(wj, v.z, acc.z);
                acc.w = fmaf(wj, v.w, acc.w);
            } else {
                acc.x += v.x; acc.y += v.y; acc.z += v.z; acc.w += v.w;
            }
        }
    }
    *reinterpret_cast<float4*>(agg + (size_t)d * FEAT + lane * 4) = acc;
}

// ---------------------------------------------------------------------------
// Tensor-core fused GraphConv GEMM (tf32 mma.sync, 3-term split for fp32 acc):
//   out[m,n] = act( A1[m,:]@W1[:,n] + (HAS2 ? A2[m,:]@W2[:,n] : 0) + bias[n] )
// 256 thr / 8 warps; warp tile 32x32 (2x4 m16n8k8 frags); block BM x BN;
// BK=16 double-buffered via cp.async. Split: a=ah+al (tf32), D += ah*bh +
// ah*bl + al*bh  -> ~2^-22 error, safe vs 1e-3 gate.
// ---------------------------------------------------------------------------
template <int BM, int BN, bool HAS2, bool RELU>
__global__ __launch_bounds__(256)
void gemm_tf32(const float* __restrict__ A1, const float* __restrict__ W1,
               const float* __restrict__ A2, const float* __restrict__ W2,
               const float* __restrict__ bias,
               float* __restrict__ out, int M) {
    constexpr int BK = 16, K = 128;
    constexpr int TPP = K / BK;                 // 8 chunks per operand pass
    constexpr int NT  = HAS2 ? 2 * TPP : TPP;
    constexpr int WC  = BN / 32, WR = BM / 32;
    static_assert(WR * WC == 8, "8 warps");
    constexpr int BKP = BK + 4;   // 20 floats = 80B rows: 16B-aligned, conflict-free frag reads
    constexpr int BNP = BN + 4;   // 132/68 floats: 16B-aligned rows

    __shared__ float sA[2][BM][BKP];
    __shared__ float sB[2][BK][BNP];

    const int t    = threadIdx.x;
    const int lane = t & 31, w = t >> 5;
    const int wm = (w / WC) * 32, wn = (w % WC) * 32;
    const int g = lane >> 2, c = lane & 3;
    const int rowBase = blockIdx.x * BM;

    auto stage = [&](int tt) {
        const float* A = (HAS2 && tt >= TPP) ? A2 : A1;
        const float* W = (HAS2 && tt >= TPP) ? W2 : W1;
        const int kt  = (tt % TPP) * BK;
        const int buf = tt & 1;
        // A tile: BM x BK floats = BM*4 quads
#pragma unroll
        for (int q = t; q < BM * (BK / 4); q += 256) {
            int r  = q >> 2;
            int kk = (q & 3) * 4;
            const float* src = A + (size_t)(rowBase + r) * K + kt + kk;
            uint32_t dst = (uint32_t)__cvta_generic_to_shared(&sA[buf][r][kk]);
            int sz = (rowBase + r < M) ? 16 : 0;   // zero-fill OOB rows
            asm volatile("cp.async.ca.shared.global [%0], [%1], 16, %2;"
                         :: "r"(dst), "l"(src), "r"(sz));
        }
        // B tile: BK x BN floats = BK*BN/4 quads
#pragma unroll
        for (int q = t; q < BK * (BN / 4); q += 256) {
            int kr = q / (BN / 4);
            int nc = (q % (BN / 4)) * 4;
            const float* src = W + (size_t)(kt + kr) * BN + nc;
            uint32_t dst = (uint32_t)__cvta_generic_to_shared(&sB[buf][kr][nc]);
            asm volatile("cp.async.ca.shared.global [%0], [%1], 16;"
                         :: "r"(dst), "l"(src));
        }
        asm volatile("cp.async.commit_group;");
    };

    float acc[2][4][4] = {};   // [mi][ni][frag]

    stage(0);
#pragma unroll 1
    for (int tt = 0; tt < NT; ++tt) {
        if (tt + 1 < NT) {
            stage(tt + 1);
            asm volatile("cp.async.wait_group 1;");
        } else {
            asm volatile("cp.async.wait_group 0;");
        }
        __syncthreads();
        const int cur = tt & 1;
#pragma unroll
        for (int k8 = 0; k8 < BK / 8; ++k8) {
            const int k0 = k8 * 8;
            // B fragments (hi/lo) for the 4 n-tiles
            uint32_t bh[4][2], bl[4][2];
#pragma unroll
            for (int ni = 0; ni < 4; ++ni)
#pragma unroll
                for (int h = 0; h < 2; ++h) {
                    float b = sB[cur][k0 + c + 4 * h][wn + ni * 8 + g];
                    uint32_t hb = f2tf32(b);
                    bh[ni][h] = hb;
                    bl[ni][h] = f2tf32(b - __uint_as_float(hb));
                }
            // A fragments per m-tile, then MMAs
#pragma unroll
            for (int mi = 0; mi < 2; ++mi) {
                float a0 = sA[cur][wm + mi * 16 + g    ][k0 + c];
                float a1 = sA[cur][wm + mi * 16 + g + 8][k0 + c];
                float a2 = sA[cur][wm + mi * 16 + g    ][k0 + c + 4];
                float a3 = sA[cur][wm + mi * 16 + g + 8][k0 + c + 4];
                uint32_t ah[4], al[4];
                ah[0] = f2tf32(a0); al[0] = f2tf32(a0 - __uint_as_float(ah[0]));
                ah[1] = f2tf32(a1); al[1] = f2tf32(a1 - __uint_as_float(ah[1]));
                ah[2] = f2tf32(a2); al[2] = f2tf32(a2 - __uint_as_float(ah[2]));
                ah[3] = f2tf32(a3); al[3] = f2tf32(a3 - __uint_as_float(ah[3]));
#pragma unroll
                for (int ni = 0; ni < 4; ++ni) {
                    mma8(acc[mi][ni], ah, bh[ni]);
                    mma8(acc[mi][ni], ah, bl[ni]);
                    mma8(acc[mi][ni], al, bh[ni]);
                }
            }
        }
        __syncthreads();   // all reads done before next stage overwrites this buf
    }

    // --- epilogue: bias (+ReLU) + store ---
#pragma unroll
    for (int mi = 0; mi < 2; ++mi) {
        int r0 = rowBase + wm + mi * 16 + g;
#pragma unroll
        for (int ni = 0; ni < 4; ++ni) {
            int col = wn + ni * 8 + 2 * c;
            float b0 = __ldg(bias + col), b1 = __ldg(bias + col + 1);
            float o0 = acc[mi][ni][0] + b0, o1 = acc[mi][ni][1] + b1;
            float o2 = acc[mi][ni][2] + b0, o3 = acc[mi][ni][3] + b1;
            if (RELU) {
                o0 = fmaxf(o0, 0.f); o1 = fmaxf(o1, 0.f);
                o2 = fmaxf(o2, 0.f); o3 = fmaxf(o3, 0.f);
            }
            if (r0 < M)
                *reinterpret_cast<float2*>(out + (size_t)r0 * BN + col) = make_float2(o0, o1);
            if (r0 + 8 < M)
                *reinterpret_cast<float2*>(out + (size_t)(r0 + 8) * BN + col) = make_float2(o2, o3);
        }
    }
}

// ---------------------------------------------------------------------------
// Launch
// ---------------------------------------------------------------------------
extern "C" void kernel_launch(void* const* d_in, const int* in_sizes, int n_in,
                              void* d_out, int out_size) {
    const float* x_meas  = (const float*)d_in[0];
    const float* x_dem   = (const float*)d_in[1];
    const int*   src_m   = (const int*)  d_in[2];
    const int*   dst_m   = (const int*)  d_in[3];
    const int*   src_b   = (const int*)  d_in[4];
    const int*   dst_b   = (const int*)  d_in[5];
    const float* eweight = (const float*)d_in[6];
    const float* W_rel1  = (const float*)d_in[7];
    const float* b_rel1  = (const float*)d_in[8];
    const float* W_root1 = (const float*)d_in[9];
    const float* W_rel2  = (const float*)d_in[10];
    const float* b_rel2  = (const float*)d_in[11];
    const float* W_root2 = (const float*)d_in[12];
    const float* W_rel3  = (const float*)d_in[13];
    const float* b_rel3  = (const float*)d_in[14];
    const float* W_root3 = (const float*)d_in[15];
    const float* W_lin   = (const float*)d_in[16];
    const float* b_lin   = (const float*)d_in[17];
    float* out = (float*)d_out;

    const int n_m = in_sizes[0] / FEAT;
    const int n_d = in_sizes[1] / FEAT;
    const int E   = in_sizes[2];

    float *agg1, *agg2, *agg3, *movie, *user1, *user2;
    cudaGetSymbolAddress((void**)&agg1,  g_agg1);
    cudaGetSymbolAddress((void**)&agg2,  g_agg2);
    cudaGetSymbolAddress((void**)&agg3,  g_agg3);
    cudaGetSymbolAddress((void**)&movie, g_movie);
    cudaGetSymbolAddress((void**)&user1, g_user1);
    cudaGetSymbolAddress((void**)&user2, g_user2);
    int *off_m, *off_b, *perm_m, *perm_b;
    cudaGetSymbolAddress((void**)&off_m,  g_off_m);
    cudaGetSymbolAddress((void**)&off_b,  g_off_b);
    cudaGetSymbolAddress((void**)&perm_m, g_perm_m);
    cudaGetSymbolAddress((void**)&perm_b, g_perm_b);

    const int eb   = (E + 255) / 256;
    const int nb_m = (n_m + SCAN_CHUNK - 1) / SCAN_CHUNK;   // <= 32
    const int nb_b = (n_d + SCAN_CHUNK - 1) / SCAN_CHUNK;   // <= 32

    // --- CSR build: zero, hist, fused reduce+scan, offsets, fill (5 launches) ---
    zero_counts_kernel<<<(n_m + 256) / 256, 256>>>(n_m, n_d);
    hist_kernel<<<eb, 256>>>(dst_m, dst_b, eweight, E);
    csr_reduce_scan<<<nb_m + nb_b, 256>>>(n_m, n_d, nb_m, nb_b);
    csr_offsets<<<nb_m + nb_b, 256>>>(n_m, n_d, nb_m);
    fill_kernel<<<eb, 256>>>(dst_m, dst_b, E);

    // --- Layer 1 aggregations (gather, no atomics) --- [6th launch: profiled]
    agg_gather<false><<<(n_m + 7) / 8, 256>>>(x_meas, src_m, perm_m, off_m, agg1, n_m);
    agg_gather<true ><<<(n_d + 7) / 8, 256>>>(x_meas, src_b, perm_b, off_b, agg2, n_d);

    // --- Layer 1/2 GEMMs (tf32 tensor cores, 3-term split) ---
    gemm_tf32<64, 128, true, true><<<(n_m + 63) / 64, 256>>>(
        agg1, W_rel1, x_meas, W_root1, b_rel1, movie, n_m);
    gemm_tf32<64, 128, true, true><<<(n_d + 63) / 64, 256>>>(
        agg2, W_rel2, x_dem, W_root2, b_rel2, user1, n_d);

    // --- Layer 3 aggregation (reuses bipartite CSR) + GEMM ---
    agg_gather<true><<<(n_d + 7) / 8, 256>>>(movie, src_b, perm_b, off_b, agg3, n_d);
    gemm_tf32<64, 128, true, true><<<(n_d + 63) / 64, 256>>>(
        agg3, W_rel3, user1, W_root3, b_rel3, user2, n_d);

    // --- Output projection (N=64) ---
    gemm_tf32<128, 64, false, false><<<(n_d + 127) / 128, 256>>>(
        user2, W_lin, nullptr, nullptr, b_lin, out, n_d);
}